// round 5
// baseline (speedup 1.0000x reference)
#include <cuda_runtime.h>

// Problem constants (fixed by setup_inputs): B=8, N=20, K=5, Q=15, D=1024
#define BB     8
#define NN     20
#define KSUP   5
#define QQ     15
#define DD     1024
#define ROWS   (KSUP + QQ)        // 20 rows per (b,n)
#define NQ     (NN * QQ)          // 300 queries per batch
#define NQTOT  (BB * NQ)          // 2400 queries total
#define WARPS  16
#define THREADS 512
#define GRID   (NQTOT / WARPS)    // 150 blocks, 1 query/warp, single wave

// 1 ulonglong2 = 16 B = 4 floats. A D=1024 row = 256 ulonglong2.
#define ROW_U2 256

typedef unsigned long long u64;

// Scratch (device globals — no allocation allowed)
__device__ float g_proto[BB * NN * DD];   // 640 KB, L2-resident
__device__ float g_termp[BB * NN];

// ---- packed f32x2 helpers (sm_103a) ----
__device__ __forceinline__ u64 mul2(u64 a, u64 b) {
    u64 r; asm("mul.rn.f32x2 %0,%1,%2;" : "=l"(r) : "l"(a), "l"(b)); return r;
}
__device__ __forceinline__ u64 add2(u64 a, u64 b) {
    u64 r; asm("add.rn.f32x2 %0,%1,%2;" : "=l"(r) : "l"(a), "l"(b)); return r;
}
__device__ __forceinline__ u64 fma2_(u64 a, u64 b, u64 c) {
    u64 r; asm("fma.rn.f32x2 %0,%1,%2,%3;" : "=l"(r) : "l"(a), "l"(b), "l"(c)); return r;
}
__device__ __forceinline__ u64 abs2(u64 a) {      // clears both sign bits (alu pipe)
    u64 r; asm("and.b64 %0,%1,0x7FFFFFFF7FFFFFFF;" : "=l"(r) : "l"(a)); return r;
}
__device__ __forceinline__ u64 neg2(u64 a) {
    u64 r; asm("xor.b64 %0,%1,0x8000000080000000;" : "=l"(r) : "l"(a)); return r;
}
__device__ __forceinline__ float hsum2(u64 a) {
    float x, y; asm("mov.b64 {%0,%1},%2;" : "=f"(x), "=f"(y) : "l"(a)); return x + y;
}

// ---------------------------------------------------------------------------
// K1: proto[b,n,:] = mean_j support, term_p[b,n] = proto . w0
// ---------------------------------------------------------------------------
__global__ __launch_bounds__(256) void proto_kernel(
    const float* __restrict__ emb, const float* __restrict__ weight)
{
    int bn = blockIdx.x;             // b*20 + n
    int t  = threadIdx.x;            // float4 index 0..255
    const float4* base = reinterpret_cast<const float4*>(emb) + (size_t)bn * ROWS * 256;

    float4 s = base[t];
#pragma unroll
    for (int j = 1; j < KSUP; j++) {
        float4 v = base[j * 256 + t];
        s.x += v.x; s.y += v.y; s.z += v.z; s.w += v.w;
    }
    s.x *= 0.2f; s.y *= 0.2f; s.z *= 0.2f; s.w *= 0.2f;
    reinterpret_cast<float4*>(g_proto)[(size_t)bn * 256 + t] = s;

    float4 w0 = reinterpret_cast<const float4*>(weight)[t];
    float tp = s.x * w0.x + s.y * w0.y + s.z * w0.z + s.w * w0.w;
#pragma unroll
    for (int off = 16; off; off >>= 1) tp += __shfl_xor_sync(0xFFFFFFFFu, tp, off);

    __shared__ float red[8];
    if ((t & 31) == 0) red[t >> 5] = tp;
    __syncthreads();
    if (t == 0) {
        float r = 0.f;
#pragma unroll
        for (int w = 0; w < 8; w++) r += red[w];
        g_termp[bn] = r;
    }
}

// ---------------------------------------------------------------------------
// Main: 150 blocks x 512 threads (16 warps), ONE query per warp, single wave.
// Packed f32x2 math: per 4 d per n = 6 fma-pipe ops + 2 LOP3.64 (alu pipe,
// idle). n-accumulators in registers, two passes of 10 to stay under the
// 128-reg cap; lane reductions deferred to pass end (independent butterflies).
// ---------------------------------------------------------------------------
__global__ __launch_bounds__(THREADS, 1) void relnet_kernel(
    const float* __restrict__ emb,
    const float* __restrict__ weight,
    const float* __restrict__ bias,
    float* __restrict__ out)
{
    extern __shared__ float smem[];
    ulonglong2* sP  = reinterpret_cast<ulonglong2*>(smem);              // 20*256 u2 = 81920 B
    ulonglong2* sW2 = reinterpret_cast<ulonglong2*>(smem + NN * DD);    // 256 u2   =  4096 B
    float*      sTp = smem + NN * DD + 1024;                            // 20 floats

    const int tid  = threadIdx.x;
    const int lane = tid & 31;
    const int warp = tid >> 5;

    const int g   = blockIdx.x * WARPS + warp;   // global query id 0..2399
    const int bMy = g / NQ;
    const int q   = g - bMy * NQ;                // query idx within batch
    const int bLo = (blockIdx.x * WARPS) / NQ;
    const int bHi = (blockIdx.x * WARPS + WARPS - 1) / NQ;

    const ulonglong2* embu = reinterpret_cast<const ulonglong2*>(emb);
    const ulonglong2* w1u  = reinterpret_cast<const ulonglong2*>(weight) + 1 * ROW_U2;
    const ulonglong2* w2u  = reinterpret_cast<const ulonglong2*>(weight) + 2 * ROW_U2;
    const ulonglong2* w3u  = reinterpret_cast<const ulonglong2*>(weight) + 3 * ROW_U2;
    const ulonglong2* gPu  = reinterpret_cast<const ulonglong2*>(g_proto);
    const float bi = bias[0];

    // ---- load this warp's query into registers: -q (packed) and q*w3 ----
    const int qrow = (bMy * NN + q / QQ) * ROWS + KSUP + q % QQ;
    const ulonglong2* r = embu + (size_t)qrow * ROW_U2;

    u64 qn[16], cv[16];
    u64 tqp = 0ull;
#pragma unroll
    for (int i = 0; i < 8; i++) {
        const int idx = i * 32 + lane;
        ulonglong2 a  = r[idx];
        ulonglong2 w3 = w3u[idx];
        ulonglong2 w1 = w1u[idx];
        qn[2*i]   = neg2(a.x);        qn[2*i+1] = neg2(a.y);
        cv[2*i]   = mul2(a.x, w3.x);  cv[2*i+1] = mul2(a.y, w3.y);
        tqp = fma2_(a.x, w1.x, tqp);  tqp = fma2_(a.y, w1.y, tqp);
    }
    float tq = hsum2(tqp);
#pragma unroll
    for (int off = 16; off; off >>= 1) tq += __shfl_xor_sync(0xFFFFFFFFu, tq, off);

    float* o = out + ((size_t)bMy * NQ + q) * NN;

#pragma unroll 1
    for (int b = bLo; b <= bHi; b++) {
        __syncthreads();   // protect smem from previous iteration's readers
        for (int idx = tid; idx < NN * ROW_U2; idx += THREADS)
            sP[idx] = gPu[(size_t)b * NN * ROW_U2 + idx];
        if (tid < 256) sW2[tid] = w2u[tid];
        if (tid < NN)  sTp[tid] = g_termp[b * NN + tid];
        __syncthreads();
        if (bMy != b) continue;

#pragma unroll 1
        for (int pass = 0; pass < 2; pass++) {
            u64 acc[10];
#pragma unroll
            for (int n = 0; n < 10; n++) acc[n] = 0ull;

            const ulonglong2* pb = sP + pass * 10 * ROW_U2 + lane;
#pragma unroll
            for (int i = 0; i < 8; i++) {
                const ulonglong2 w2 = sW2[i * 32 + lane];
#pragma unroll
                for (int n = 0; n < 10; n++) {
                    const ulonglong2 p = pb[n * ROW_U2 + i * 32];
                    u64 d0 = abs2(add2(p.x, qn[2*i]));
                    acc[n] = fma2_(d0,  w2.x,      acc[n]);
                    acc[n] = fma2_(p.x, cv[2*i],   acc[n]);
                    u64 d1 = abs2(add2(p.y, qn[2*i+1]));
                    acc[n] = fma2_(d1,  w2.y,      acc[n]);
                    acc[n] = fma2_(p.y, cv[2*i+1], acc[n]);
                }
            }

            // deferred reductions: 10 independent butterflies, full ILP
#pragma unroll
            for (int n = 0; n < 10; n++) {
                float s = hsum2(acc[n]);
#pragma unroll
                for (int off = 16; off; off >>= 1)
                    s += __shfl_xor_sync(0xFFFFFFFFu, s, off);
                if (lane == 0) {
                    const int nn = pass * 10 + n;
                    o[nn] = s + sTp[nn] + tq + bi;
                }
            }
        }
    }
}

// ---------------------------------------------------------------------------
// Launch
// ---------------------------------------------------------------------------
static const int SMEM_BYTES = (NN * DD + 1024 + 32) * (int)sizeof(float); // 86,144 B

extern "C" void kernel_launch(void* const* d_in, const int* in_sizes, int n_in,
                              void* d_out, int out_size)
{
    const float* emb    = (const float*)d_in[0];
    const float* weight = (const float*)d_in[1];
    const float* bias   = (const float*)d_in[2];
    float* out          = (float*)d_out;

    cudaFuncSetAttribute(relnet_kernel,
                         cudaFuncAttributeMaxDynamicSharedMemorySize, SMEM_BYTES);

    proto_kernel<<<BB * NN, 256>>>(emb, weight);
    relnet_kernel<<<GRID, THREADS, SMEM_BYTES>>>(emb, weight, bias, out);
}